// round 7
// baseline (speedup 1.0000x reference)
#include <cuda_runtime.h>

// ZapBench volume sampler: quadrilinear (trilinear spatial + linear temporal)
// frames: (T=3, Z=72, Y=512, X=1024) fp32, coords: (N, 4) fp32 [z, y, x, t]
// out: (N, 1) fp32
//
// Pipeline: atomic-free counting sort of point INDICES into 864 bins
// (t innermost), then a gather kernel (2 pts/thread) with float4-window loads.
// Sample kernel is L1tex-wavefront bound (~11 wf/pt); sort passes are
// latency-bound -> 512-thread CTAs + fewer bins for coalesced scatter stores.

#define T_DIM 3
#define Z_DIM 72
#define Y_DIM 512
#define X_DIM 1024

#define NBINS (9 * 8 * 4 * 3)   // (z/8, y/64, x/256) spatial, t0 innermost = 864
#define CAP   (1 << 22)         // 4194304 points
#define NCTA  512
#define CHUNK_THREADS 512

__device__ unsigned int   g_hist2d[NBINS * NCTA];   // [bin][cta]
__device__ unsigned int   g_bintotal[NBINS];
__device__ unsigned int   g_binbase[NBINS];
__device__ unsigned short g_bins[CAP];
__device__ unsigned int   g_sorted_idx[CAP];

__device__ __forceinline__ int compute_bin(float4 c)
{
    float t_abs = c.w * 3.0f;
    int t0 = min(max((int)t_abs, 0), 2);
    int zc = min(max((int)(c.x * (float)(Z_DIM - 1)), 0), Z_DIM - 1) >> 3;   // 0..8
    int yc = min(max((int)(c.y * (float)(Y_DIM - 1)), 0), Y_DIM - 1) >> 6;   // 0..7
    int xc = min(max((int)(c.z * (float)(X_DIM - 1)), 0), X_DIM - 1) >> 8;   // 0..3
    return (((zc * 8 + yc) * 4 + xc) * 3) + t0;   // t innermost
}

__global__ void __launch_bounds__(CHUNK_THREADS)
hist_kernel(const float4* __restrict__ coords, int n, int chunk)
{
    __shared__ unsigned int s_cnt[NBINS];
    for (int b = threadIdx.x; b < NBINS; b += blockDim.x) s_cnt[b] = 0;
    __syncthreads();

    int start = blockIdx.x * chunk;
    int end   = min(start + chunk, n);

    for (int i = start + threadIdx.x; i < end; i += blockDim.x) {
        float4 c = __ldcs(&coords[i]);
        int bin = compute_bin(c);
        g_bins[i] = (unsigned short)bin;
        atomicAdd(&s_cnt[bin], 1u);
    }
    __syncthreads();

    unsigned int cta = blockIdx.x;
    for (int b = threadIdx.x; b < NBINS; b += blockDim.x) {
        g_hist2d[(unsigned int)b * NCTA + cta] = s_cnt[b];
    }
}

// Scan pass 1: one CTA per bin, exclusive scan of NCTA counts in place.
__global__ void __launch_bounds__(NCTA)
scan1_kernel()
{
    __shared__ unsigned int buf[2][NCTA];
    int b = blockIdx.x;
    int t = threadIdx.x;

    unsigned int v = g_hist2d[(unsigned int)b * NCTA + t];
    buf[0][t] = v;
    __syncthreads();

    int src = 0;
    for (int d = 1; d < NCTA; d <<= 1) {
        unsigned int x = buf[src][t];
        if (t >= d) x += buf[src][t - d];
        buf[src ^ 1][t] = x;
        __syncthreads();
        src ^= 1;
    }
    unsigned int inclusive = buf[src][t];
    g_hist2d[(unsigned int)b * NCTA + t] = inclusive - v;
    if (t == NCTA - 1) g_bintotal[b] = inclusive;
}

// Scan pass 2: exclusive scan over NBINS bin totals.
__global__ void __launch_bounds__(1024)
scan2_kernel()
{
    __shared__ unsigned int buf[2][1024];
    int t = threadIdx.x;

    unsigned int h0 = (2 * t     < NBINS) ? g_bintotal[2 * t]     : 0u;
    unsigned int h1 = (2 * t + 1 < NBINS) ? g_bintotal[2 * t + 1] : 0u;
    unsigned int sum = h0 + h1;

    buf[0][t] = sum;
    __syncthreads();
    int src = 0;
    for (int d = 1; d < 1024; d <<= 1) {
        unsigned int v = buf[src][t];
        if (t >= d) v += buf[src][t - d];
        buf[src ^ 1][t] = v;
        __syncthreads();
        src ^= 1;
    }
    unsigned int inclusive = buf[src][t];
    unsigned int base = inclusive - sum;

    if (2 * t     < NBINS) g_binbase[2 * t]     = base;
    if (2 * t + 1 < NBINS) g_binbase[2 * t + 1] = base + h0;
}

// Scatter: indices only, exact precomputed positions, no global atomics.
__global__ void __launch_bounds__(CHUNK_THREADS)
scatter_kernel(int n, int chunk)
{
    __shared__ unsigned int s_base[NBINS];
    __shared__ unsigned int s_cnt[NBINS];

    unsigned int cta = blockIdx.x;
    for (int b = threadIdx.x; b < NBINS; b += blockDim.x) {
        s_base[b] = g_binbase[b] + g_hist2d[(unsigned int)b * NCTA + cta];
        s_cnt[b]  = 0;
    }
    __syncthreads();

    int start = blockIdx.x * chunk;
    int end   = min(start + chunk, n);

    for (int i = start + threadIdx.x; i < end; i += blockDim.x) {
        int bin = g_bins[i];
        unsigned int pos = s_base[bin] + atomicAdd(&s_cnt[bin], 1u);
        g_sorted_idx[pos] = (unsigned int)i;
    }
}

__device__ __forceinline__ float f4_sel(float4 q, int k)
{
    float lo = (k & 1) ? q.y : q.x;
    float hi = (k & 1) ? q.w : q.z;
    return (k & 2) ? hi : lo;
}

// Sample both x-texels of one row using an aligned float4 window.
__device__ __forceinline__ float row_lerp(
    const float4* __restrict__ row, int b4, int off, int a4, int ao, float wx)
{
    float4 q = __ldg(row + b4);
    float4 q2 = q;
    if (a4 != b4) q2 = __ldg(row + a4);
    float c0 = f4_sel(q, off);
    float c1 = f4_sel(q2, ao);
    return fmaf(wx, c1 - c0, c0);
}

__device__ __forceinline__ float trilerp_slice4(
    const float* __restrict__ f, int t,
    int z0, int z1, int y0, int y1,
    int b4, int off, int a4, int ao,
    float wz, float wy, float wx)
{
    const int tb = t * Z_DIM;
    const float4* r00 = (const float4*)f + ((long)((tb + z0) * Y_DIM + y0) << 8);
    const float4* r01 = (const float4*)f + ((long)((tb + z0) * Y_DIM + y1) << 8);
    const float4* r10 = (const float4*)f + ((long)((tb + z1) * Y_DIM + y0) << 8);
    const float4* r11 = (const float4*)f + ((long)((tb + z1) * Y_DIM + y1) << 8);

    float c00 = row_lerp(r00, b4, off, a4, ao, wx);
    float c01 = row_lerp(r01, b4, off, a4, ao, wx);
    float c10 = row_lerp(r10, b4, off, a4, ao, wx);
    float c11 = row_lerp(r11, b4, off, a4, ao, wx);

    float c0 = fmaf(wy, c01 - c00, c00);
    float c1 = fmaf(wy, c11 - c10, c10);
    return fmaf(wz, c1 - c0, c0);
}

__device__ __forceinline__ float sample_point(
    const float4 c, const float* __restrict__ frames)
{
    float t_abs = c.w * 3.0f;
    int t0 = min(max((int)t_abs, 0), 2);
    int t1 = min(t0 + 1, T_DIM - 1);
    float w = t_abs - (float)t0;

    float sz = c.x * (float)(Z_DIM - 1);
    float sy = c.y * (float)(Y_DIM - 1);
    float sx = c.z * (float)(X_DIM - 1);

    int iz = (int)sz;   // inputs in [0,1): trunc == floor
    int iy = (int)sy;
    int ix = (int)sx;

    float wz = sz - (float)iz;
    float wy = sy - (float)iy;
    float wx = sx - (float)ix;

    int z0 = max(0, min(iz, Z_DIM - 1));
    int y0 = max(0, min(iy, Y_DIM - 1));
    int x0 = max(0, min(ix, X_DIM - 1));
    int z1 = min(z0 + 1, Z_DIM - 1);
    int y1 = min(y0 + 1, Y_DIM - 1);
    int x1 = min(x0 + 1, X_DIM - 1);

    int b4 = x0 >> 2, off = x0 & 3;
    int a4 = x1 >> 2, ao  = x1 & 3;

    float val0 = trilerp_slice4(frames, t0, z0, z1, y0, y1, b4, off, a4, ao, wz, wy, wx);

    if (t1 != t0) {
        float val1 = trilerp_slice4(frames, t1, z0, z1, y0, y1, b4, off, a4, ao, wz, wy, wx);
        return fmaf(w, val1 - val0, val0);
    }
    return val0;
}

// 2 points per thread: uint2 idx load (halves idx wavefronts), streaming
// loads for idx/coords and streaming store for out keep one-touch data from
// evicting volume lines out of L2.
__global__ void __launch_bounds__(256)
sample_sorted_kernel(const float4* __restrict__ coords,
                     const float*  __restrict__ frames,
                     float*        __restrict__ out,
                     int n)
{
    int j = (blockIdx.x * blockDim.x + threadIdx.x) * 2;
    if (j + 1 < n) {
        uint2 ii = __ldcs((const uint2*)&g_sorted_idx[j]);
        float4 c0 = __ldcs(&coords[ii.x]);
        float4 c1 = __ldcs(&coords[ii.y]);
        float r0 = sample_point(c0, frames);
        float r1 = sample_point(c1, frames);
        __stcs(&out[ii.x], r0);
        __stcs(&out[ii.y], r1);
    } else if (j < n) {
        unsigned int i = __ldcs(&g_sorted_idx[j]);
        float4 c = __ldcs(&coords[i]);
        __stcs(&out[i], sample_point(c, frames));
    }
}

__global__ void __launch_bounds__(256)
sample_direct_kernel(const float4* __restrict__ coords,
                     const float*  __restrict__ frames,
                     float*        __restrict__ out,
                     int n)
{
    int i = blockIdx.x * blockDim.x + threadIdx.x;
    if (i >= n) return;
    float4 c = __ldg(&coords[i]);
    out[i] = sample_point(c, frames);
}

extern "C" void kernel_launch(void* const* d_in, const int* in_sizes, int n_in,
                              void* d_out, int out_size)
{
    const float4* coords = (const float4*)d_in[0];
    const float*  frames = (const float*)d_in[1];
    float* out = (float*)d_out;

    int n = in_sizes[0] / 4;   // coords is (N,4) floats

    if (n > CAP) {
        int blocks = (n + 255) / 256;
        sample_direct_kernel<<<blocks, 256>>>(coords, frames, out, n);
        return;
    }

    int chunk = (n + NCTA - 1) / NCTA;
    int pair_threads = (n + 1) / 2;
    int sample_blocks = (pair_threads + 255) / 256;

    hist_kernel<<<NCTA, CHUNK_THREADS>>>(coords, n, chunk);
    scan1_kernel<<<NBINS, NCTA>>>();
    scan2_kernel<<<1, 1024>>>();
    scatter_kernel<<<NCTA, CHUNK_THREADS>>>(n, chunk);
    sample_sorted_kernel<<<sample_blocks, 256>>>(coords, frames, out, n);
}

// round 8
// speedup vs baseline: 1.0697x; 1.0697x over previous
#include <cuda_runtime.h>

// ZapBench volume sampler: quadrilinear (trilinear spatial + linear temporal)
// frames: (T=3, Z=72, Y=512, X=1024) fp32, coords: (N, 4) fp32 [z, y, x, t]
// out: (N, 1) fp32
//
// Pipeline: atomic-free counting sort of point INDICES into 1728 bins
// (t innermost), then a gather kernel with float4-window loads.
// R7 lesson: coarser bins / 2pt-per-thread / __ldcs regressed the sample
// kernel; keep R6's sample + binning, keep only the 512-thread hist/scatter.

#define T_DIM 3
#define Z_DIM 72
#define Y_DIM 512
#define X_DIM 1024

#define NBINS (9 * 8 * 8 * 3)   // (z/8, y/64, x/128) spatial, t0 innermost
#define CAP   (1 << 22)         // 4194304 points
#define NCTA  512
#define CHUNK_THREADS 512

__device__ unsigned int   g_hist2d[NBINS * NCTA];   // [bin][cta]
__device__ unsigned int   g_bintotal[NBINS];
__device__ unsigned int   g_binbase[NBINS];
__device__ unsigned short g_bins[CAP];
__device__ unsigned int   g_sorted_idx[CAP];

__device__ __forceinline__ int compute_bin(float4 c)
{
    float t_abs = c.w * 3.0f;
    int t0 = min(max((int)t_abs, 0), 2);
    int zc = min(max((int)(c.x * (float)(Z_DIM - 1)), 0), Z_DIM - 1) >> 3;   // 0..8
    int yc = min(max((int)(c.y * (float)(Y_DIM - 1)), 0), Y_DIM - 1) >> 6;   // 0..7
    int xc = min(max((int)(c.z * (float)(X_DIM - 1)), 0), X_DIM - 1) >> 7;   // 0..7
    return (((zc * 8 + yc) * 8 + xc) * 3) + t0;   // t innermost
}

__global__ void __launch_bounds__(CHUNK_THREADS)
hist_kernel(const float4* __restrict__ coords, int n, int chunk)
{
    __shared__ unsigned int s_cnt[NBINS];
    for (int b = threadIdx.x; b < NBINS; b += blockDim.x) s_cnt[b] = 0;
    __syncthreads();

    int start = blockIdx.x * chunk;
    int end   = min(start + chunk, n);

    for (int i = start + threadIdx.x; i < end; i += blockDim.x) {
        float4 c = __ldg(&coords[i]);
        int bin = compute_bin(c);
        g_bins[i] = (unsigned short)bin;
        atomicAdd(&s_cnt[bin], 1u);
    }
    __syncthreads();

    unsigned int cta = blockIdx.x;
    for (int b = threadIdx.x; b < NBINS; b += blockDim.x) {
        g_hist2d[(unsigned int)b * NCTA + cta] = s_cnt[b];
    }
}

// Scan pass 1: one CTA per bin, exclusive scan of NCTA counts in place.
__global__ void __launch_bounds__(NCTA)
scan1_kernel()
{
    __shared__ unsigned int buf[2][NCTA];
    int b = blockIdx.x;
    int t = threadIdx.x;

    unsigned int v = g_hist2d[(unsigned int)b * NCTA + t];
    buf[0][t] = v;
    __syncthreads();

    int src = 0;
    for (int d = 1; d < NCTA; d <<= 1) {
        unsigned int x = buf[src][t];
        if (t >= d) x += buf[src][t - d];
        buf[src ^ 1][t] = x;
        __syncthreads();
        src ^= 1;
    }
    unsigned int inclusive = buf[src][t];
    g_hist2d[(unsigned int)b * NCTA + t] = inclusive - v;
    if (t == NCTA - 1) g_bintotal[b] = inclusive;
}

// Scan pass 2: exclusive scan over NBINS bin totals.
__global__ void __launch_bounds__(1024)
scan2_kernel()
{
    __shared__ unsigned int buf[2][1024];
    int t = threadIdx.x;

    unsigned int h0 = (2 * t     < NBINS) ? g_bintotal[2 * t]     : 0u;
    unsigned int h1 = (2 * t + 1 < NBINS) ? g_bintotal[2 * t + 1] : 0u;
    unsigned int sum = h0 + h1;

    buf[0][t] = sum;
    __syncthreads();
    int src = 0;
    for (int d = 1; d < 1024; d <<= 1) {
        unsigned int v = buf[src][t];
        if (t >= d) v += buf[src][t - d];
        buf[src ^ 1][t] = v;
        __syncthreads();
        src ^= 1;
    }
    unsigned int inclusive = buf[src][t];
    unsigned int base = inclusive - sum;

    if (2 * t     < NBINS) g_binbase[2 * t]     = base;
    if (2 * t + 1 < NBINS) g_binbase[2 * t + 1] = base + h0;
}

// Scatter: indices only, exact precomputed positions, no global atomics.
__global__ void __launch_bounds__(CHUNK_THREADS)
scatter_kernel(int n, int chunk)
{
    __shared__ unsigned int s_base[NBINS];
    __shared__ unsigned int s_cnt[NBINS];

    unsigned int cta = blockIdx.x;
    for (int b = threadIdx.x; b < NBINS; b += blockDim.x) {
        s_base[b] = g_binbase[b] + g_hist2d[(unsigned int)b * NCTA + cta];
        s_cnt[b]  = 0;
    }
    __syncthreads();

    int start = blockIdx.x * chunk;
    int end   = min(start + chunk, n);

    for (int i = start + threadIdx.x; i < end; i += blockDim.x) {
        int bin = g_bins[i];
        unsigned int pos = s_base[bin] + atomicAdd(&s_cnt[bin], 1u);
        g_sorted_idx[pos] = (unsigned int)i;
    }
}

__device__ __forceinline__ float f4_sel(float4 q, int k)
{
    float lo = (k & 1) ? q.y : q.x;
    float hi = (k & 1) ? q.w : q.z;
    return (k & 2) ? hi : lo;
}

// Sample both x-texels of one row using an aligned float4 window.
__device__ __forceinline__ float row_lerp(
    const float4* __restrict__ row, int b4, int off, int a4, int ao, float wx)
{
    float4 q = __ldg(row + b4);
    float4 q2 = q;
    if (a4 != b4) q2 = __ldg(row + a4);
    float c0 = f4_sel(q, off);
    float c1 = f4_sel(q2, ao);
    return fmaf(wx, c1 - c0, c0);
}

__device__ __forceinline__ float trilerp_slice4(
    const float* __restrict__ f, int t,
    int z0, int z1, int y0, int y1,
    int b4, int off, int a4, int ao,
    float wz, float wy, float wx)
{
    const int tb = t * Z_DIM;
    const float4* r00 = (const float4*)f + ((long)((tb + z0) * Y_DIM + y0) << 8);
    const float4* r01 = (const float4*)f + ((long)((tb + z0) * Y_DIM + y1) << 8);
    const float4* r10 = (const float4*)f + ((long)((tb + z1) * Y_DIM + y0) << 8);
    const float4* r11 = (const float4*)f + ((long)((tb + z1) * Y_DIM + y1) << 8);

    float c00 = row_lerp(r00, b4, off, a4, ao, wx);
    float c01 = row_lerp(r01, b4, off, a4, ao, wx);
    float c10 = row_lerp(r10, b4, off, a4, ao, wx);
    float c11 = row_lerp(r11, b4, off, a4, ao, wx);

    float c0 = fmaf(wy, c01 - c00, c00);
    float c1 = fmaf(wy, c11 - c10, c10);
    return fmaf(wz, c1 - c0, c0);
}

__device__ __forceinline__ float sample_point(
    const float4 c, const float* __restrict__ frames)
{
    float t_abs = c.w * 3.0f;
    int t0 = min(max((int)t_abs, 0), 2);
    int t1 = min(t0 + 1, T_DIM - 1);
    float w = t_abs - (float)t0;

    float sz = c.x * (float)(Z_DIM - 1);
    float sy = c.y * (float)(Y_DIM - 1);
    float sx = c.z * (float)(X_DIM - 1);

    int iz = (int)sz;   // inputs in [0,1): trunc == floor
    int iy = (int)sy;
    int ix = (int)sx;

    float wz = sz - (float)iz;
    float wy = sy - (float)iy;
    float wx = sx - (float)ix;

    int z0 = max(0, min(iz, Z_DIM - 1));
    int y0 = max(0, min(iy, Y_DIM - 1));
    int x0 = max(0, min(ix, X_DIM - 1));
    int z1 = min(z0 + 1, Z_DIM - 1);
    int y1 = min(y0 + 1, Y_DIM - 1);
    int x1 = min(x0 + 1, X_DIM - 1);

    int b4 = x0 >> 2, off = x0 & 3;
    int a4 = x1 >> 2, ao  = x1 & 3;

    float val0 = trilerp_slice4(frames, t0, z0, z1, y0, y1, b4, off, a4, ao, wz, wy, wx);

    if (t1 != t0) {
        float val1 = trilerp_slice4(frames, t1, z0, z1, y0, y1, b4, off, a4, ao, wz, wy, wx);
        return fmaf(w, val1 - val0, val0);
    }
    return val0;
}

__global__ void __launch_bounds__(256)
sample_sorted_kernel(const float4* __restrict__ coords,
                     const float*  __restrict__ frames,
                     float*        __restrict__ out,
                     int n)
{
    int j = blockIdx.x * blockDim.x + threadIdx.x;
    if (j >= n) return;

    unsigned int i = __ldg(&g_sorted_idx[j]);
    float4 c = __ldg(&coords[i]);
    out[i] = sample_point(c, frames);
}

__global__ void __launch_bounds__(256)
sample_direct_kernel(const float4* __restrict__ coords,
                     const float*  __restrict__ frames,
                     float*        __restrict__ out,
                     int n)
{
    int i = blockIdx.x * blockDim.x + threadIdx.x;
    if (i >= n) return;
    float4 c = __ldg(&coords[i]);
    out[i] = sample_point(c, frames);
}

extern "C" void kernel_launch(void* const* d_in, const int* in_sizes, int n_in,
                              void* d_out, int out_size)
{
    const float4* coords = (const float4*)d_in[0];
    const float*  frames = (const float*)d_in[1];
    float* out = (float*)d_out;

    int n = in_sizes[0] / 4;   // coords is (N,4) floats
    int blocks = (n + 255) / 256;

    if (n > CAP) {
        sample_direct_kernel<<<blocks, 256>>>(coords, frames, out, n);
        return;
    }

    int chunk = (n + NCTA - 1) / NCTA;

    hist_kernel<<<NCTA, CHUNK_THREADS>>>(coords, n, chunk);
    scan1_kernel<<<NBINS, NCTA>>>();
    scan2_kernel<<<1, 1024>>>();
    scatter_kernel<<<NCTA, CHUNK_THREADS>>>(n, chunk);
    sample_sorted_kernel<<<blocks, 256>>>(coords, frames, out, n);
}